// round 14
// baseline (speedup 1.0000x reference)
#include <cuda_runtime.h>
#include <math.h>

#define B_  32
#define N_  512
#define L_  12
#define U_  64
#define HOR 12

// ---------------------------------------------------------------------------
// Scratch layout (floats)
// ---------------------------------------------------------------------------
constexpr long SZ_NN  = (long)B_ * N_ * N_;          // 8388608
constexpr long GT     = (long)B_ * N_;               // 16384

constexpr long OFF_A0T   = 0;
constexpr long OFF_A1T   = OFF_A0T + SZ_NN;
constexpr long OFF_PT    = OFF_A1T + SZ_NN;               // (B,512,2048)
constexpr long OFF_TCA   = OFF_PT + 4 * SZ_NN;            // (B,128,2048) ping
constexpr long OFF_TCB   = OFF_TCA + (long)B_*128*2048;   // (B,128,2048) pong
constexpr long OFF_ZD    = OFF_TCB + (long)B_*128*2048;   // (B,64,2048) zeros
constexpr long OFF_THXT  = OFF_ZD + (long)B_*64*2048;     // (B,64,2048) dec step0
constexpr long OFF_TRHXT = OFF_THXT + (long)B_*64*2048;   // (B,64,2048)
constexpr long OFF_TTX   = OFF_TRHXT + (long)B_*64*2048;  // (B,24,2048)
constexpr long OFF_TDEC  = OFF_TTX + (long)B_*24*2048;    // (B,2048)
constexpr long OFF_HISTT = OFF_TDEC + (long)B_*2048;      // (24,16384)
constexpr long OFF_U     = OFF_HISTT + 24*GT;             // (16384,64) row
constexpr long OFF_HIS   = OFF_U + 64*GT;                 // (16384,64) row
constexpr long OFF_FC1   = OFF_HIS + 64*GT;               // (16384,256)
constexpr long OFF_DEC   = OFF_FC1 + 256*GT;              // (16384)
constexpr long OFF_RS0   = OFF_DEC + GT;
constexpr long OFF_RS1   = OFF_RS0 + GT;
constexpr long OFF_RHXT  = OFF_RS1 + GT;                  // (64,16384)
constexpr long OFF_H     = OFF_RHXT + 64*GT;              // 8 buffers x 1M
constexpr long SZ_H1 = 64*GT;
constexpr long SCRATCH_TOTAL = OFF_H + 8*SZ_H1;

__device__ float g_scratch[SCRATCH_TOTAL];

// ---------------------------------------------------------------------------
// Support construction (transposed supports)
// ---------------------------------------------------------------------------
__global__ void rowsum_k(const float* __restrict__ adj, float* __restrict__ rs0) {
    int w = (blockIdx.x * blockDim.x + threadIdx.x) >> 5;
    int lane = threadIdx.x & 31;
    if (w >= B_ * N_) return;
    const float* base = adj + (long)w * N_;
    float s = 0.f;
    for (int j = lane; j < N_; j += 32) s += base[j];
    #pragma unroll
    for (int o = 16; o; o >>= 1) s += __shfl_xor_sync(0xffffffffu, s, o);
    if (lane == 0) rs0[w] = s + 1.0f;
}

__global__ void colsum_k(const float* __restrict__ adj, float* __restrict__ rs1) {
    int idx = blockIdx.x * blockDim.x + threadIdx.x;
    if (idx >= B_ * N_) return;
    int b = idx >> 9, i = idx & 511;
    const float* base = adj + (long)b * N_ * N_ + i;
    float s = 1.0f;
    for (int j = 0; j < N_; j++) s += base[(long)j * N_];
    rs1[idx] = s;
}

__global__ void fill_supports_T(const float* __restrict__ adj,
                                const float* __restrict__ rs0,
                                const float* __restrict__ rs1,
                                float* __restrict__ A0T, float* __restrict__ A1T,
                                float* __restrict__ PT) {
    long idx = (long)blockIdx.x * blockDim.x + threadIdx.x;
    if (idx >= (long)B_ * N_ * N_) return;
    int i = (int)(idx & 511);
    long t = idx >> 9;
    int j = (int)(t & 511);
    int b = (int)(t >> 9);
    float d = (i == j) ? 1.f : 0.f;
    float a_ij = adj[((long)b * N_ + i) * N_ + j];
    float a_ji = adj[idx];
    float v0 = (a_ij + d) / rs0[b * N_ + i];
    float v1 = (a_ji + d) / rs1[b * N_ + i];
    A0T[idx] = v0;
    A1T[idx] = v1;
    PT[(long)b * 512 * 2048 + (long)j * 2048 + i] = v0;
}

// ---------------------------------------------------------------------------
// Generic batched SGEMM: C[b] = A[b] @ B[b], tile BMxBNx16.
// epi: 0 none, 1: 2x - I, 2: 2x - extra[b] (ld 512), 3: bias + relu
// ---------------------------------------------------------------------------
template<int BM, int BN, int TM, int TN>
__global__ __launch_bounds__(256, 2)
void sgemm_t(int K,
             const float* __restrict__ A, int lda, long sA,
             const float* __restrict__ Bm, int ldb, long sB,
             float* __restrict__ C, int ldc, long sC,
             int epi, const float* __restrict__ extra, long sE,
             const float* __restrict__ bias)
{
    constexpr int BK = 16;
    constexpr int TX = BN / TN;
    constexpr int AF = BM / 64;
    constexpr int BF = BN / 64;
    __shared__ float As[2][BK][BM + 4];
    __shared__ float Bs[2][BK][BN];
    int bz = blockIdx.z;
    const float* Ab = A + (long)bz * sA;
    const float* Bb = Bm + (long)bz * sB;
    float* Cb = C + (long)bz * sC;
    int row0 = blockIdx.y * BM, col0 = blockIdx.x * BN;
    int tid = threadIdx.x;
    int tx = tid % TX, ty = tid / TX;

    int aRow[AF], aCol[AF], bRow[BF], bCol[BF];
    #pragma unroll
    for (int s = 0; s < AF; s++) { int idx = tid + s * 256; aRow[s] = idx >> 2; aCol[s] = (idx & 3) << 2; }
    #pragma unroll
    for (int s = 0; s < BF; s++) { int idx = tid + s * 256; bRow[s] = idx / (BN / 4); bCol[s] = (idx % (BN / 4)) << 2; }

    float4 aR[AF], bR[BF];

    auto ldT = [&](int k0) {
        #pragma unroll
        for (int s = 0; s < AF; s++) {
            const float* p = Ab + (long)(row0 + aRow[s]) * lda + k0 + aCol[s];
            if (k0 + BK <= K) aR[s] = *(const float4*)p;
            else {
                int k = k0 + aCol[s];
                aR[s].x = (k     < K) ? p[0] : 0.f;
                aR[s].y = (k + 1 < K) ? p[1] : 0.f;
                aR[s].z = (k + 2 < K) ? p[2] : 0.f;
                aR[s].w = (k + 3 < K) ? p[3] : 0.f;
            }
        }
        #pragma unroll
        for (int s = 0; s < BF; s++) {
            int k = k0 + bRow[s];
            if (k < K) bR[s] = *(const float4*)(Bb + (long)k * ldb + col0 + bCol[s]);
            else bR[s] = make_float4(0.f, 0.f, 0.f, 0.f);
        }
    };
    auto stT = [&](int buf) {
        #pragma unroll
        for (int s = 0; s < AF; s++) {
            As[buf][aCol[s]    ][aRow[s]] = aR[s].x;
            As[buf][aCol[s] + 1][aRow[s]] = aR[s].y;
            As[buf][aCol[s] + 2][aRow[s]] = aR[s].z;
            As[buf][aCol[s] + 3][aRow[s]] = aR[s].w;
        }
        #pragma unroll
        for (int s = 0; s < BF; s++)
            *(float4*)&Bs[buf][bRow[s]][bCol[s]] = bR[s];
    };

    float acc[TM][TN];
    #pragma unroll
    for (int i = 0; i < TM; i++)
        #pragma unroll
        for (int j = 0; j < TN; j++) acc[i][j] = 0.f;

    int ntile = (K + BK - 1) / BK;
    ldT(0); stT(0); __syncthreads();
    for (int t = 0; t < ntile; t++) {
        if (t + 1 < ntile) ldT((t + 1) * BK);
        int buf = t & 1;
        #pragma unroll
        for (int kk = 0; kk < BK; kk++) {
            float ar[TM], br[TN];
            #pragma unroll
            for (int i = 0; i < TM / 4; i++)
                *(float4*)&ar[i * 4] = *(const float4*)&As[buf][kk][ty * TM + i * 4];
            #pragma unroll
            for (int j = 0; j < TN / 4; j++)
                *(float4*)&br[j * 4] = *(const float4*)&Bs[buf][kk][tx * TN + j * 4];
            #pragma unroll
            for (int i = 0; i < TM; i++)
                #pragma unroll
                for (int j = 0; j < TN; j++) acc[i][j] += ar[i] * br[j];
        }
        if (t + 1 < ntile) stT(buf ^ 1);
        __syncthreads();
    }

    #pragma unroll
    for (int i = 0; i < TM; i++) {
        int r = row0 + ty * TM + i;
        #pragma unroll
        for (int j = 0; j < TN; j++) {
            int c = col0 + tx * TN + j;
            float v = acc[i][j];
            if (epi == 1) v = 2.f * v - ((r == c) ? 1.f : 0.f);
            else if (epi == 2) v = 2.f * v - extra[(long)bz * sE + (long)r * N_ + c];
            else if (epi == 3) { v += bias[c]; v = fmaxf(v, 0.f); }
            Cb[(long)r * ldc + c] = v;
        }
    }
}

// ---------------------------------------------------------------------------
// Transposed diffusion GEMM (occupancy-tuned, min MINB blocks/SM):
//   TT[b](MR x 2048) = Aeff[b](MR x 512) @ PT[b](512 x 2048)
// ---------------------------------------------------------------------------
template<int BM, int BN, int TM, int TN, int MINB>
__global__ __launch_bounds__(256, MINB)
void difft_k(int MR, int asplit,
             const float* __restrict__ src1,
             const float* __restrict__ src2,
             const float* __restrict__ PT,
             float* __restrict__ TT, long sT)
{
    constexpr int BK = 16;
    constexpr int TX = BN / TN;
    constexpr int AE = BM * BK / 256;
    constexpr int BF = BK * BN / 1024;
    __shared__ float As[2][BK][BM + 4];
    __shared__ float Bs[2][BK][BN];

    int bz = blockIdx.z;
    int row0 = blockIdx.y * BM, col0 = blockIdx.x * BN;
    int tid = threadIdx.x;
    int tx = tid % TX, ty = tid / TX;

    int am = tid % BM;
    int ak0 = (tid / BM) * AE;
    int r = row0 + am;
    const float* srow = nullptr;
    if (r < asplit) srow = src1 + (long)r * GT + (long)bz * 512;
    else if (r < MR) srow = src2 + (long)(r - asplit) * GT + (long)bz * 512;

    int bRow[BF], bCol[BF];
    #pragma unroll
    for (int s = 0; s < BF; s++) {
        int idx = tid + s * 256;
        bRow[s] = idx / (BN / 4);
        bCol[s] = (idx % (BN / 4)) << 2;
    }

    float aR[AE];
    float4 bR[BF];
    const float* Pb = PT + (long)bz * 512 * 2048;

    auto ldT = [&](int k0) {
        if (srow) {
            #pragma unroll
            for (int e = 0; e < AE; e += 4)
                *(float4*)&aR[e] = *(const float4*)(srow + k0 + ak0 + e);
        } else {
            #pragma unroll
            for (int e = 0; e < AE; e++) aR[e] = 0.f;
        }
        #pragma unroll
        for (int s = 0; s < BF; s++)
            bR[s] = *(const float4*)(Pb + (long)(k0 + bRow[s]) * 2048 + col0 + bCol[s]);
    };
    auto stT = [&](int buf) {
        #pragma unroll
        for (int e = 0; e < AE; e++) As[buf][ak0 + e][am] = aR[e];
        #pragma unroll
        for (int s = 0; s < BF; s++) *(float4*)&Bs[buf][bRow[s]][bCol[s]] = bR[s];
    };

    float acc[TM][TN];
    #pragma unroll
    for (int i = 0; i < TM; i++)
        #pragma unroll
        for (int j = 0; j < TN; j++) acc[i][j] = 0.f;

    constexpr int NT = 512 / BK;
    ldT(0); stT(0); __syncthreads();
    for (int t = 0; t < NT; t++) {
        if (t + 1 < NT) ldT((t + 1) * BK);
        int buf = t & 1;
        #pragma unroll
        for (int kk = 0; kk < BK; kk++) {
            float ar[TM], br[TN];
            #pragma unroll
            for (int i = 0; i < TM / 4; i++)
                *(float4*)&ar[i * 4] = *(const float4*)&As[buf][kk][ty * TM + i * 4];
            #pragma unroll
            for (int j = 0; j < TN / 4; j++)
                *(float4*)&br[j * 4] = *(const float4*)&Bs[buf][kk][tx * TN + j * 4];
            #pragma unroll
            for (int i = 0; i < TM; i++)
                #pragma unroll
                for (int j = 0; j < TN; j++) acc[i][j] += ar[i] * br[j];
        }
        if (t + 1 < NT) stT(buf ^ 1);
        __syncthreads();
    }

    float* Tb = TT + (long)bz * sT;
    #pragma unroll
    for (int i = 0; i < TM; i++) {
        int rr = row0 + ty * TM + i;
        if (rr < MR) {
            #pragma unroll
            for (int j = 0; j < TN; j++) {
                int c = col0 + tx * TN + j;
                Tb[(long)rr * 2048 + c] = acc[i][j];
            }
        }
    }
}

// ---------------------------------------------------------------------------
// Contraction GEMM, transposed (coalesced) A-gather. 3 blocks/SM.
// ---------------------------------------------------------------------------
template<int BM, int BN, int TM, int TN>
__global__ __launch_bounds__(256, 3)
void catgemmT_k(int K, int f_in,
                const float* __restrict__ Xa, long sXa, int snXa, long sjXa,
                const float* __restrict__ XbT,
                const float* __restrict__ Ta, long sTa,
                const float* __restrict__ Tb, long sTb,
                const float* __restrict__ W, int ldW,
                const float* __restrict__ bias,
                const float* __restrict__ HXrow,
                const float* __restrict__ Urow,
                float* __restrict__ RHXT, float* __restrict__ Uout,
                float* __restrict__ HoutT, float* __restrict__ HoutR,
                int mode)
{
    constexpr int BK = 16;
    constexpr int TX = BN / TN;
    constexpr int AE = BM * BK / 256;
    constexpr int BF = BK * BN / 1024;
    __shared__ float As[2][BK][BM + 4];
    __shared__ float Bs[2][BK][BN];

    int row0 = blockIdx.y * BM;
    int col0 = blockIdx.x * BN;
    int tid = threadIdx.x;
    int tx = tid % TX, ty = tid / TX;

    int am = tid % BM;
    int ak0 = (tid / BM) * AE;
    int growL = row0 + am;
    int bL = growL >> 9, nL = growL & 511;

    int bRow[BF], bCol[BF];
    #pragma unroll
    for (int s = 0; s < BF; s++) {
        int idx = tid + s * 256;
        bRow[s] = idx / (BN / 4);
        bCol[s] = (idx % (BN / 4)) << 2;
    }

    float aR[AE];
    float4 bR[BF];

    auto ldT = [&](int k0) {
        #pragma unroll
        for (int e = 0; e < AE; e++) {
            int k = k0 + ak0 + e;
            float v = 0.f;
            if (k < K) {
                int j = k / 5;
                int m = k - j * 5;
                if (m == 0) {
                    v = (j < f_in) ? Xa[(long)bL * sXa + (long)nL * snXa + (long)j * sjXa]
                                   : XbT[(long)(j - f_in) * GT + growL];
                } else {
                    long off = (long)(m - 1) * 512 + nL;
                    v = (j < f_in) ? Ta[(long)bL * sTa + (long)j * 2048 + off]
                                   : Tb[(long)bL * sTb + (long)(j - f_in) * 2048 + off];
                }
            }
            aR[e] = v;
        }
        #pragma unroll
        for (int s = 0; s < BF; s++) {
            int k = k0 + bRow[s];
            if (k < K) bR[s] = *(const float4*)(W + (long)k * ldW + col0 + bCol[s]);
            else bR[s] = make_float4(0.f, 0.f, 0.f, 0.f);
        }
    };
    auto stT = [&](int buf) {
        #pragma unroll
        for (int e = 0; e < AE; e++) As[buf][ak0 + e][am] = aR[e];
        #pragma unroll
        for (int s = 0; s < BF; s++) *(float4*)&Bs[buf][bRow[s]][bCol[s]] = bR[s];
    };

    float acc[TM][TN];
    #pragma unroll
    for (int i = 0; i < TM; i++)
        #pragma unroll
        for (int j = 0; j < TN; j++) acc[i][j] = 0.f;

    int ntile = (K + BK - 1) / BK;
    ldT(0); stT(0); __syncthreads();
    for (int t = 0; t < ntile; t++) {
        if (t + 1 < ntile) ldT((t + 1) * BK);
        int buf = t & 1;
        #pragma unroll
        for (int kk = 0; kk < BK; kk++) {
            float ar[TM], br[TN];
            #pragma unroll
            for (int i = 0; i < TM / 4; i++)
                *(float4*)&ar[i * 4] = *(const float4*)&As[buf][kk][ty * TM + i * 4];
            #pragma unroll
            for (int j = 0; j < TN / 4; j++)
                *(float4*)&br[j * 4] = *(const float4*)&Bs[buf][kk][tx * TN + j * 4];
            #pragma unroll
            for (int i = 0; i < TM; i++)
                #pragma unroll
                for (int j = 0; j < TN; j++) acc[i][j] += ar[i] * br[j];
        }
        if (t + 1 < ntile) stT(buf ^ 1);
        __syncthreads();
    }

    #pragma unroll
    for (int i = 0; i < TM; i++) {
        int grow = row0 + ty * TM + i;
        #pragma unroll
        for (int j = 0; j < TN; j++) {
            int c = col0 + tx * TN + j;
            float v = acc[i][j] + bias[c];
            if (mode == 0) {
                v = 1.f / (1.f + expf(-v));
                if (c < 64) RHXT[(long)c * GT + grow] = v * HXrow[(long)grow * 64 + c];
                else        Uout[(long)grow * 64 + (c - 64)] = v;
            } else {
                float cc = tanhf(v);
                float u = Urow[(long)grow * 64 + c];
                float hx = HXrow[(long)grow * 64 + c];
                float h = u * hx + (1.f - u) * cc;
                HoutT[(long)c * GT + grow] = h;
                HoutR[(long)grow * 64 + c] = h;
            }
        }
    }
}

// ---------------------------------------------------------------------------
// Small kernels
// ---------------------------------------------------------------------------
__global__ void hist_t_k(const float* __restrict__ hd, float* __restrict__ histT) {
    int idx = blockIdx.x * blockDim.x + threadIdx.x;
    if (idx >= 24 * B_ * N_) return;
    int n = idx & 511;
    int t2 = idx >> 9;
    int b = t2 & 31;
    int row = t2 >> 5;
    int t = row >> 1, c = row & 1;
    histT[(long)row * GT + b * 512 + n] =
        hd[(((long)b * L_ + t) * N_ + n) * 2 + c];
}

__global__ void dec_diff_k(const float* __restrict__ PT,
                           const float* __restrict__ dec,
                           float* __restrict__ TDEC) {
    int b = blockIdx.y;
    int r = blockIdx.x * 256 + threadIdx.x;
    __shared__ float ds[512];
    ds[threadIdx.x] = dec[b * 512 + threadIdx.x];
    ds[threadIdx.x + 256] = dec[b * 512 + threadIdx.x + 256];
    __syncthreads();
    const float* p = PT + (long)b * 512 * 2048 + r;
    float acc = 0.f;
    #pragma unroll 8
    for (int j = 0; j < 512; j++) acc += ds[j] * p[(long)j * 2048];
    TDEC[(long)b * 2048 + r] = acc;
}

__global__ void add_his_k(float* __restrict__ h0r, float* __restrict__ h0T,
                          float* __restrict__ h1r, float* __restrict__ h1T,
                          const float* __restrict__ his) {
    int i = blockIdx.x * blockDim.x + threadIdx.x;
    if (i >= B_ * N_ * U_) return;
    int grow = i >> 6, c = i & 63;
    float v = his[i];
    h0r[i] += v; h1r[i] += v;
    h0T[(long)c * GT + grow] += v;
    h1T[(long)c * GT + grow] += v;
}

__global__ void projT_k(const float* __restrict__ hT, const float* __restrict__ W,
                        const float* __restrict__ bptr, float* __restrict__ decin,
                        float* __restrict__ out, int t) {
    int grow = blockIdx.x * blockDim.x + threadIdx.x;
    if (grow >= B_ * N_) return;
    float s = bptr[0];
    #pragma unroll
    for (int c = 0; c < 64; c++) s += hT[(long)c * GT + grow] * W[c];
    decin[grow] = s;
    out[(long)grow * HOR + t] = s;
}

// ---------------------------------------------------------------------------
// Host orchestration
// ---------------------------------------------------------------------------
struct HPair { float* r; float* t; };

static void diff64(const float* src1, const float* PT, float* TT) {
    difft_k<64, 128, 8, 4, 4><<<dim3(16, 1, B_), 256>>>(64, 64, src1, nullptr, PT, TT, (long)64 * 2048);
}

// layer-0 cell: hx diffusion supplied externally (Tb, sTb).
static void cell0(float* S, int f_in,
                  const float* Xa, long sXa, int snXa, long sjXa,
                  const float* Ta, long sTa,
                  const float* Tb, long sTb,
                  HPair hx, HPair hout,
                  const float* Wg, const float* bg,
                  const float* Wc, const float* bc) {
    float* PT    = S + OFF_PT;
    float* TRHXT = S + OFF_TRHXT;
    float* RHXT  = S + OFF_RHXT;
    float* Ub    = S + OFF_U;
    int K = (f_in + 64) * 5;

    catgemmT_k<64, 128, 4, 8><<<dim3(1, 256), 256>>>(
        K, f_in, Xa, sXa, snXa, sjXa, hx.t, Ta, sTa, Tb, sTb,
        Wg, 128, bg, hx.r, nullptr, RHXT, Ub, nullptr, nullptr, 0);
    diff64(RHXT, PT, TRHXT);
    catgemmT_k<64, 64, 4, 4><<<dim3(1, 256), 256>>>(
        K, f_in, Xa, sXa, snXa, sjXa, RHXT, Ta, sTa, TRHXT, (long)64 * 2048,
        Wc, 64, bc, hx.r, Ub, nullptr, nullptr, hout.t, hout.r, 1);
}

// layer-1 cell: merged diffusion of [xinT ; hxT] into tcatt (ping-pong).
static void cell1(float* S, const float* xinT, HPair hx, HPair hout,
                  float* tcatt,
                  const float* Wg, const float* bg,
                  const float* Wc, const float* bc) {
    float* PT    = S + OFF_PT;
    float* TRHXT = S + OFF_TRHXT;
    float* RHXT  = S + OFF_RHXT;
    float* Ub    = S + OFF_U;
    const long sTC = (long)128 * 2048;
    int K = 640;

    difft_k<64, 128, 8, 4, 4><<<dim3(16, 2, B_), 256>>>(
        128, 64, xinT, hx.t, PT, tcatt, sTC);
    catgemmT_k<64, 128, 4, 8><<<dim3(1, 256), 256>>>(
        K, 64, xinT, 512, 1, (long)GT, hx.t, tcatt, sTC, tcatt + 64 * 2048, sTC,
        Wg, 128, bg, hx.r, nullptr, RHXT, Ub, nullptr, nullptr, 0);
    diff64(RHXT, PT, TRHXT);
    catgemmT_k<64, 64, 4, 4><<<dim3(1, 256), 256>>>(
        K, 64, xinT, 512, 1, (long)GT, RHXT, tcatt, sTC, TRHXT, (long)64 * 2048,
        Wc, 64, bc, hx.r, Ub, nullptr, nullptr, hout.t, hout.r, 1);
}

extern "C" void kernel_launch(void* const* d_in, const int* in_sizes, int n_in,
                              void* d_out, int out_size) {
    (void)in_sizes; (void)n_in; (void)out_size;
    float* S = nullptr;
    cudaGetSymbolAddress((void**)&S, g_scratch);

    const float* hd   = (const float*)d_in[0];
    const float* hs   = (const float*)d_in[1];
    const float* adj  = (const float*)d_in[2];
    const float* e0Wg = (const float*)d_in[3];
    const float* e0bg = (const float*)d_in[4];
    const float* e0Wc = (const float*)d_in[5];
    const float* e0bc = (const float*)d_in[6];
    const float* e1Wg = (const float*)d_in[7];
    const float* e1bg = (const float*)d_in[8];
    const float* e1Wc = (const float*)d_in[9];
    const float* e1bc = (const float*)d_in[10];
    const float* d0Wg = (const float*)d_in[11];
    const float* d0bg = (const float*)d_in[12];
    const float* d0Wc = (const float*)d_in[13];
    const float* d0bc = (const float*)d_in[14];
    const float* d1Wg = (const float*)d_in[15];
    const float* d1bg = (const float*)d_in[16];
    const float* d1Wc = (const float*)d_in[17];
    const float* d1bc = (const float*)d_in[18];
    const float* prW  = (const float*)d_in[19];
    const float* prb  = (const float*)d_in[20];
    const float* f1W  = (const float*)d_in[21];
    const float* f1b  = (const float*)d_in[22];
    const float* f2W  = (const float*)d_in[23];
    const float* f2b  = (const float*)d_in[24];
    float* out = (float*)d_out;

    float* A0T  = S + OFF_A0T;
    float* A1T  = S + OFF_A1T;
    float* PT   = S + OFF_PT;
    float* TCA  = S + OFF_TCA;
    float* TCB  = S + OFF_TCB;
    float* ZD   = S + OFF_ZD;
    float* THXT = S + OFF_THXT;
    float* TTX  = S + OFF_TTX;
    float* TDEC = S + OFF_TDEC;
    float* HISTT= S + OFF_HISTT;
    float* HIS  = S + OFF_HIS;
    float* FC1  = S + OFF_FC1;
    float* DEC  = S + OFF_DEC;
    float* RS0  = S + OFF_RS0;
    float* RS1  = S + OFF_RS1;

    HPair H[4];
    for (int i = 0; i < 4; i++) {
        H[i].r  = S + OFF_H + (2 * i) * SZ_H1;
        H[i].t  = S + OFF_H + (2 * i + 1) * SZ_H1;
    }

    cudaMemsetAsync(S + OFF_H, 0, 4 * SZ_H1 * sizeof(float));
    cudaMemsetAsync(DEC, 0, (long)B_ * N_ * sizeof(float));
    cudaMemsetAsync(ZD, 0, (long)B_ * 64 * 2048 * sizeof(float));

    // ---- supports + transposed stacked diffusion operator PT ----
    rowsum_k<<<(B_ * N_ * 32 + 255) / 256, 256>>>(adj, RS0);
    colsum_k<<<(B_ * N_ + 255) / 256, 256>>>(adj, RS1);
    fill_supports_T<<<(int)(((long)B_ * N_ * N_ + 255) / 256), 256>>>(adj, RS0, RS1, A0T, A1T, PT);
    const long NB = (long)N_ * N_;
    const long PBx = (long)512 * 2048;
    dim3 gp(4, 4, B_);
    sgemm_t<128, 128, 8, 8><<<gp, 256>>>(512, A0T, 512, NB, A0T, 512, NB,
                                         PT + 512, 2048, PBx, 1, nullptr, 0, nullptr);
    sgemm_t<128, 128, 8, 8><<<gp, 256>>>(512, A0T, 512, NB, A1T, 512, NB,
                                         PT + 1024, 2048, PBx, 0, nullptr, 0, nullptr);
    sgemm_t<128, 128, 8, 8><<<gp, 256>>>(512, PT + 1024, 2048, PBx, A1T, 512, NB,
                                         PT + 1536, 2048, PBx, 2, A0T, NB, nullptr);

    // ---- fc_his ----
    sgemm_t<128, 128, 8, 8><<<dim3(2, 128, 1), 256>>>(96, hs, 96, 0, f1W, 256, 0,
                                                      FC1, 256, 0, 3, nullptr, 0, f1b);
    sgemm_t<128, 64, 8, 4><<<dim3(1, 128, 1), 256>>>(256, FC1, 256, 0, f2W, 64, 0,
                                                     HIS, 64, 0, 3, nullptr, 0, f2b);

    // ---- encoder layer-0 input diffusions, all timesteps at once ----
    hist_t_k<<<(24 * B_ * N_ + 255) / 256, 256>>>(hd, HISTT);
    difft_k<64, 128, 8, 4, 4><<<dim3(16, 1, B_), 256>>>(24, 24, HISTT, nullptr, PT,
                                                        TTX, (long)24 * 2048);

    HPair hc0 = H[0], hc1 = H[1], hn0 = H[2], hn1 = H[3];
    float* prevTC = nullptr;

    // ---- encoder ----
    for (int t = 0; t < L_; t++) {
        const float* Tb = (t == 0) ? ZD : prevTC;
        long sTb = (t == 0) ? (long)64 * 2048 : (long)128 * 2048;
        cell0(S, 2,
              hd + (long)t * N_ * 2, (long)L_ * N_ * 2, 2, 1,
              TTX + (long)t * 2 * 2048, (long)24 * 2048,
              Tb, sTb,
              hc0, hn0, e0Wg, e0bg, e0Wc, e0bc);
        float* tc = (prevTC == TCA) ? TCB : TCA;
        cell1(S, hn0.t, hc1, hn1, tc, e1Wg, e1bg, e1Wc, e1bc);
        prevTC = tc;
        HPair tmp;
        tmp = hc0; hc0 = hn0; hn0 = tmp;
        tmp = hc1; hc1 = hn1; hn1 = tmp;
    }
    add_his_k<<<(B_ * N_ * U_ + 255) / 256, 256>>>(hc0.r, hc0.t, hc1.r, hc1.t, HIS);

    // ---- decoder ----
    for (int t = 0; t < HOR; t++) {
        dec_diff_k<<<dim3(8, B_), 256>>>(PT, DEC, TDEC);
        const float* Tb;
        long sTb;
        if (t == 0) {
            diff64(hc0.t, PT, THXT);
            Tb = THXT; sTb = (long)64 * 2048;
        } else {
            Tb = prevTC; sTb = (long)128 * 2048;
        }
        cell0(S, 1,
              DEC, 512, 1, 0,
              TDEC, (long)2048,
              Tb, sTb,
              hc0, hn0, d0Wg, d0bg, d0Wc, d0bc);
        float* tc = (prevTC == TCA) ? TCB : TCA;
        cell1(S, hn0.t, hc1, hn1, tc, d1Wg, d1bg, d1Wc, d1bc);
        prevTC = tc;
        projT_k<<<(B_ * N_ + 255) / 256, 256>>>(hn1.t, prW, prb, DEC, out, t);
        HPair tmp;
        tmp = hc0; hc0 = hn0; hn0 = tmp;
        tmp = hc1; hc1 = hn1; hn1 = tmp;
    }
}

// round 15
// speedup vs baseline: 1.0386x; 1.0386x over previous
#include <cuda_runtime.h>
#include <math.h>

#define B_  32
#define N_  512
#define L_  12
#define U_  64
#define HOR 12

// ---------------------------------------------------------------------------
// Scratch layout (floats)
// ---------------------------------------------------------------------------
constexpr long SZ_NN  = (long)B_ * N_ * N_;          // 8388608
constexpr long GT     = (long)B_ * N_;               // 16384

constexpr long OFF_A0T   = 0;
constexpr long OFF_A1T   = OFF_A0T + SZ_NN;
constexpr long OFF_PT    = OFF_A1T + SZ_NN;               // (B,512,2048)
constexpr long OFF_TCA   = OFF_PT + 4 * SZ_NN;            // (B,128,2048) ping
constexpr long OFF_TCB   = OFF_TCA + (long)B_*128*2048;   // (B,128,2048) pong
constexpr long OFF_ZD    = OFF_TCB + (long)B_*128*2048;   // (B,64,2048) zeros
constexpr long OFF_THXT  = OFF_ZD + (long)B_*64*2048;     // (B,64,2048) dec step0
constexpr long OFF_TRHXT = OFF_THXT + (long)B_*64*2048;   // (B,64,2048)
constexpr long OFF_TTX   = OFF_TRHXT + (long)B_*64*2048;  // (B,24,2048)
constexpr long OFF_TDEC  = OFF_TTX + (long)B_*24*2048;    // (B,2048)
constexpr long OFF_HISTT = OFF_TDEC + (long)B_*2048;      // (24,16384)
constexpr long OFF_U     = OFF_HISTT + 24*GT;             // (16384,64) row
constexpr long OFF_HIS   = OFF_U + 64*GT;                 // (16384,64) row
constexpr long OFF_FC1   = OFF_HIS + 64*GT;               // (16384,256)
constexpr long OFF_DEC   = OFF_FC1 + 256*GT;              // (16384)
constexpr long OFF_RS0   = OFF_DEC + GT;
constexpr long OFF_RS1   = OFF_RS0 + GT;
constexpr long OFF_RHXT  = OFF_RS1 + GT;                  // (64,16384)
constexpr long OFF_H     = OFF_RHXT + 64*GT;              // 8 buffers x 1M
constexpr long SZ_H1 = 64*GT;
constexpr long SCRATCH_TOTAL = OFF_H + 8*SZ_H1;

__device__ float g_scratch[SCRATCH_TOTAL];

// ---------------------------------------------------------------------------
// Support construction (transposed supports)
// ---------------------------------------------------------------------------
__global__ void rowsum_k(const float* __restrict__ adj, float* __restrict__ rs0) {
    int w = (blockIdx.x * blockDim.x + threadIdx.x) >> 5;
    int lane = threadIdx.x & 31;
    if (w >= B_ * N_) return;
    const float* base = adj + (long)w * N_;
    float s = 0.f;
    for (int j = lane; j < N_; j += 32) s += base[j];
    #pragma unroll
    for (int o = 16; o; o >>= 1) s += __shfl_xor_sync(0xffffffffu, s, o);
    if (lane == 0) rs0[w] = s + 1.0f;
}

__global__ void colsum_k(const float* __restrict__ adj, float* __restrict__ rs1) {
    int idx = blockIdx.x * blockDim.x + threadIdx.x;
    if (idx >= B_ * N_) return;
    int b = idx >> 9, i = idx & 511;
    const float* base = adj + (long)b * N_ * N_ + i;
    float s = 1.0f;
    for (int j = 0; j < N_; j++) s += base[(long)j * N_];
    rs1[idx] = s;
}

__global__ void fill_supports_T(const float* __restrict__ adj,
                                const float* __restrict__ rs0,
                                const float* __restrict__ rs1,
                                float* __restrict__ A0T, float* __restrict__ A1T,
                                float* __restrict__ PT) {
    long idx = (long)blockIdx.x * blockDim.x + threadIdx.x;
    if (idx >= (long)B_ * N_ * N_) return;
    int i = (int)(idx & 511);
    long t = idx >> 9;
    int j = (int)(t & 511);
    int b = (int)(t >> 9);
    float d = (i == j) ? 1.f : 0.f;
    float a_ij = adj[((long)b * N_ + i) * N_ + j];
    float a_ji = adj[idx];
    float v0 = (a_ij + d) / rs0[b * N_ + i];
    float v1 = (a_ji + d) / rs1[b * N_ + i];
    A0T[idx] = v0;
    A1T[idx] = v1;
    PT[(long)b * 512 * 2048 + (long)j * 2048 + i] = v0;
}

// ---------------------------------------------------------------------------
// Generic batched SGEMM: C[b] = A[b] @ B[b], tile BMxBNx16.
// epi: 0 none, 1: 2x - I, 2: 2x - extra[b] (ld 512), 3: bias + relu
// ---------------------------------------------------------------------------
template<int BM, int BN, int TM, int TN>
__global__ __launch_bounds__(256, 2)
void sgemm_t(int K,
             const float* __restrict__ A, int lda, long sA,
             const float* __restrict__ Bm, int ldb, long sB,
             float* __restrict__ C, int ldc, long sC,
             int epi, const float* __restrict__ extra, long sE,
             const float* __restrict__ bias)
{
    constexpr int BK = 16;
    constexpr int TX = BN / TN;
    constexpr int AF = BM / 64;
    constexpr int BF = BN / 64;
    __shared__ float As[2][BK][BM + 4];
    __shared__ float Bs[2][BK][BN];
    int bz = blockIdx.z;
    const float* Ab = A + (long)bz * sA;
    const float* Bb = Bm + (long)bz * sB;
    float* Cb = C + (long)bz * sC;
    int row0 = blockIdx.y * BM, col0 = blockIdx.x * BN;
    int tid = threadIdx.x;
    int tx = tid % TX, ty = tid / TX;

    int aRow[AF], aCol[AF], bRow[BF], bCol[BF];
    #pragma unroll
    for (int s = 0; s < AF; s++) { int idx = tid + s * 256; aRow[s] = idx >> 2; aCol[s] = (idx & 3) << 2; }
    #pragma unroll
    for (int s = 0; s < BF; s++) { int idx = tid + s * 256; bRow[s] = idx / (BN / 4); bCol[s] = (idx % (BN / 4)) << 2; }

    float4 aR[AF], bR[BF];

    auto ldT = [&](int k0) {
        #pragma unroll
        for (int s = 0; s < AF; s++) {
            const float* p = Ab + (long)(row0 + aRow[s]) * lda + k0 + aCol[s];
            if (k0 + BK <= K) aR[s] = *(const float4*)p;
            else {
                int k = k0 + aCol[s];
                aR[s].x = (k     < K) ? p[0] : 0.f;
                aR[s].y = (k + 1 < K) ? p[1] : 0.f;
                aR[s].z = (k + 2 < K) ? p[2] : 0.f;
                aR[s].w = (k + 3 < K) ? p[3] : 0.f;
            }
        }
        #pragma unroll
        for (int s = 0; s < BF; s++) {
            int k = k0 + bRow[s];
            if (k < K) bR[s] = *(const float4*)(Bb + (long)k * ldb + col0 + bCol[s]);
            else bR[s] = make_float4(0.f, 0.f, 0.f, 0.f);
        }
    };
    auto stT = [&](int buf) {
        #pragma unroll
        for (int s = 0; s < AF; s++) {
            As[buf][aCol[s]    ][aRow[s]] = aR[s].x;
            As[buf][aCol[s] + 1][aRow[s]] = aR[s].y;
            As[buf][aCol[s] + 2][aRow[s]] = aR[s].z;
            As[buf][aCol[s] + 3][aRow[s]] = aR[s].w;
        }
        #pragma unroll
        for (int s = 0; s < BF; s++)
            *(float4*)&Bs[buf][bRow[s]][bCol[s]] = bR[s];
    };

    float acc[TM][TN];
    #pragma unroll
    for (int i = 0; i < TM; i++)
        #pragma unroll
        for (int j = 0; j < TN; j++) acc[i][j] = 0.f;

    int ntile = (K + BK - 1) / BK;
    ldT(0); stT(0); __syncthreads();
    for (int t = 0; t < ntile; t++) {
        if (t + 1 < ntile) ldT((t + 1) * BK);
        int buf = t & 1;
        #pragma unroll
        for (int kk = 0; kk < BK; kk++) {
            float ar[TM], br[TN];
            #pragma unroll
            for (int i = 0; i < TM / 4; i++)
                *(float4*)&ar[i * 4] = *(const float4*)&As[buf][kk][ty * TM + i * 4];
            #pragma unroll
            for (int j = 0; j < TN / 4; j++)
                *(float4*)&br[j * 4] = *(const float4*)&Bs[buf][kk][tx * TN + j * 4];
            #pragma unroll
            for (int i = 0; i < TM; i++)
                #pragma unroll
                for (int j = 0; j < TN; j++) acc[i][j] += ar[i] * br[j];
        }
        if (t + 1 < ntile) stT(buf ^ 1);
        __syncthreads();
    }

    #pragma unroll
    for (int i = 0; i < TM; i++) {
        int r = row0 + ty * TM + i;
        #pragma unroll
        for (int j = 0; j < TN; j++) {
            int c = col0 + tx * TN + j;
            float v = acc[i][j];
            if (epi == 1) v = 2.f * v - ((r == c) ? 1.f : 0.f);
            else if (epi == 2) v = 2.f * v - extra[(long)bz * sE + (long)r * N_ + c];
            else if (epi == 3) { v += bias[c]; v = fmaxf(v, 0.f); }
            Cb[(long)r * ldc + c] = v;
        }
    }
}

// ---------------------------------------------------------------------------
// Transposed diffusion GEMM (occupancy-tuned, min MINB blocks/SM):
//   TT[b](MR x 2048) = Aeff[b](MR x 512) @ PT[b](512 x 2048)
// ---------------------------------------------------------------------------
template<int BM, int BN, int TM, int TN, int MINB>
__global__ __launch_bounds__(256, MINB)
void difft_k(int MR, int asplit,
             const float* __restrict__ src1,
             const float* __restrict__ src2,
             const float* __restrict__ PT,
             float* __restrict__ TT, long sT)
{
    constexpr int BK = 16;
    constexpr int TX = BN / TN;
    constexpr int AE = BM * BK / 256;
    constexpr int BF = BK * BN / 1024;
    __shared__ float As[2][BK][BM + 4];
    __shared__ float Bs[2][BK][BN];

    int bz = blockIdx.z;
    int row0 = blockIdx.y * BM, col0 = blockIdx.x * BN;
    int tid = threadIdx.x;
    int tx = tid % TX, ty = tid / TX;

    int am = tid % BM;
    int ak0 = (tid / BM) * AE;
    int r = row0 + am;
    const float* srow = nullptr;
    if (r < asplit) srow = src1 + (long)r * GT + (long)bz * 512;
    else if (r < MR) srow = src2 + (long)(r - asplit) * GT + (long)bz * 512;

    int bRow[BF], bCol[BF];
    #pragma unroll
    for (int s = 0; s < BF; s++) {
        int idx = tid + s * 256;
        bRow[s] = idx / (BN / 4);
        bCol[s] = (idx % (BN / 4)) << 2;
    }

    float aR[AE];
    float4 bR[BF];
    const float* Pb = PT + (long)bz * 512 * 2048;

    auto ldT = [&](int k0) {
        if (srow) {
            #pragma unroll
            for (int e = 0; e < AE; e += 4)
                *(float4*)&aR[e] = *(const float4*)(srow + k0 + ak0 + e);
        } else {
            #pragma unroll
            for (int e = 0; e < AE; e++) aR[e] = 0.f;
        }
        #pragma unroll
        for (int s = 0; s < BF; s++)
            bR[s] = *(const float4*)(Pb + (long)(k0 + bRow[s]) * 2048 + col0 + bCol[s]);
    };
    auto stT = [&](int buf) {
        #pragma unroll
        for (int e = 0; e < AE; e++) As[buf][ak0 + e][am] = aR[e];
        #pragma unroll
        for (int s = 0; s < BF; s++) *(float4*)&Bs[buf][bRow[s]][bCol[s]] = bR[s];
    };

    float acc[TM][TN];
    #pragma unroll
    for (int i = 0; i < TM; i++)
        #pragma unroll
        for (int j = 0; j < TN; j++) acc[i][j] = 0.f;

    constexpr int NT = 512 / BK;
    ldT(0); stT(0); __syncthreads();
    for (int t = 0; t < NT; t++) {
        if (t + 1 < NT) ldT((t + 1) * BK);
        int buf = t & 1;
        #pragma unroll
        for (int kk = 0; kk < BK; kk++) {
            float ar[TM], br[TN];
            #pragma unroll
            for (int i = 0; i < TM / 4; i++)
                *(float4*)&ar[i * 4] = *(const float4*)&As[buf][kk][ty * TM + i * 4];
            #pragma unroll
            for (int j = 0; j < TN / 4; j++)
                *(float4*)&br[j * 4] = *(const float4*)&Bs[buf][kk][tx * TN + j * 4];
            #pragma unroll
            for (int i = 0; i < TM; i++)
                #pragma unroll
                for (int j = 0; j < TN; j++) acc[i][j] += ar[i] * br[j];
        }
        if (t + 1 < NT) stT(buf ^ 1);
        __syncthreads();
    }

    float* Tb = TT + (long)bz * sT;
    #pragma unroll
    for (int i = 0; i < TM; i++) {
        int rr = row0 + ty * TM + i;
        if (rr < MR) {
            #pragma unroll
            for (int j = 0; j < TN; j++) {
                int c = col0 + tx * TN + j;
                Tb[(long)rr * 2048 + c] = acc[i][j];
            }
        }
    }
}

// ---------------------------------------------------------------------------
// Contraction GEMM, transposed (coalesced) A-gather. MINB blocks/SM.
// ---------------------------------------------------------------------------
template<int BM, int BN, int TM, int TN, int MINB>
__global__ __launch_bounds__(256, MINB)
void catgemmT_k(int K, int f_in,
                const float* __restrict__ Xa, long sXa, int snXa, long sjXa,
                const float* __restrict__ XbT,
                const float* __restrict__ Ta, long sTa,
                const float* __restrict__ Tb, long sTb,
                const float* __restrict__ W, int ldW,
                const float* __restrict__ bias,
                const float* __restrict__ HXrow,
                const float* __restrict__ Urow,
                float* __restrict__ RHXT, float* __restrict__ Uout,
                float* __restrict__ HoutT, float* __restrict__ HoutR,
                int mode)
{
    constexpr int BK = 16;
    constexpr int TX = BN / TN;
    constexpr int AE = BM * BK / 256;
    constexpr int BF = BK * BN / 1024;
    __shared__ float As[2][BK][BM + 4];
    __shared__ float Bs[2][BK][BN];

    int row0 = blockIdx.y * BM;
    int col0 = blockIdx.x * BN;
    int tid = threadIdx.x;
    int tx = tid % TX, ty = tid / TX;

    int am = tid % BM;
    int ak0 = (tid / BM) * AE;
    int growL = row0 + am;
    int bL = growL >> 9, nL = growL & 511;

    int bRow[BF], bCol[BF];
    #pragma unroll
    for (int s = 0; s < BF; s++) {
        int idx = tid + s * 256;
        bRow[s] = idx / (BN / 4);
        bCol[s] = (idx % (BN / 4)) << 2;
    }

    float aR[AE];
    float4 bR[BF];

    auto ldT = [&](int k0) {
        #pragma unroll
        for (int e = 0; e < AE; e++) {
            int k = k0 + ak0 + e;
            float v = 0.f;
            if (k < K) {
                int j = k / 5;
                int m = k - j * 5;
                if (m == 0) {
                    v = (j < f_in) ? Xa[(long)bL * sXa + (long)nL * snXa + (long)j * sjXa]
                                   : XbT[(long)(j - f_in) * GT + growL];
                } else {
                    long off = (long)(m - 1) * 512 + nL;
                    v = (j < f_in) ? Ta[(long)bL * sTa + (long)j * 2048 + off]
                                   : Tb[(long)bL * sTb + (long)(j - f_in) * 2048 + off];
                }
            }
            aR[e] = v;
        }
        #pragma unroll
        for (int s = 0; s < BF; s++) {
            int k = k0 + bRow[s];
            if (k < K) bR[s] = *(const float4*)(W + (long)k * ldW + col0 + bCol[s]);
            else bR[s] = make_float4(0.f, 0.f, 0.f, 0.f);
        }
    };
    auto stT = [&](int buf) {
        #pragma unroll
        for (int e = 0; e < AE; e++) As[buf][ak0 + e][am] = aR[e];
        #pragma unroll
        for (int s = 0; s < BF; s++) *(float4*)&Bs[buf][bRow[s]][bCol[s]] = bR[s];
    };

    float acc[TM][TN];
    #pragma unroll
    for (int i = 0; i < TM; i++)
        #pragma unroll
        for (int j = 0; j < TN; j++) acc[i][j] = 0.f;

    int ntile = (K + BK - 1) / BK;
    ldT(0); stT(0); __syncthreads();
    for (int t = 0; t < ntile; t++) {
        if (t + 1 < ntile) ldT((t + 1) * BK);
        int buf = t & 1;
        #pragma unroll
        for (int kk = 0; kk < BK; kk++) {
            float ar[TM], br[TN];
            #pragma unroll
            for (int i = 0; i < TM / 4; i++)
                *(float4*)&ar[i * 4] = *(const float4*)&As[buf][kk][ty * TM + i * 4];
            #pragma unroll
            for (int j = 0; j < TN / 4; j++)
                *(float4*)&br[j * 4] = *(const float4*)&Bs[buf][kk][tx * TN + j * 4];
            #pragma unroll
            for (int i = 0; i < TM; i++)
                #pragma unroll
                for (int j = 0; j < TN; j++) acc[i][j] += ar[i] * br[j];
        }
        if (t + 1 < ntile) stT(buf ^ 1);
        __syncthreads();
    }

    #pragma unroll
    for (int i = 0; i < TM; i++) {
        int grow = row0 + ty * TM + i;
        #pragma unroll
        for (int j = 0; j < TN; j++) {
            int c = col0 + tx * TN + j;
            float v = acc[i][j] + bias[c];
            if (mode == 0) {
                v = 1.f / (1.f + expf(-v));
                if (c < 64) RHXT[(long)c * GT + grow] = v * HXrow[(long)grow * 64 + c];
                else        Uout[(long)grow * 64 + (c - 64)] = v;
            } else {
                float cc = tanhf(v);
                float u = Urow[(long)grow * 64 + c];
                float hx = HXrow[(long)grow * 64 + c];
                float h = u * hx + (1.f - u) * cc;
                HoutT[(long)c * GT + grow] = h;
                HoutR[(long)grow * 64 + c] = h;
            }
        }
    }
}

// ---------------------------------------------------------------------------
// Small kernels
// ---------------------------------------------------------------------------
__global__ void hist_t_k(const float* __restrict__ hd, float* __restrict__ histT) {
    int idx = blockIdx.x * blockDim.x + threadIdx.x;
    if (idx >= 24 * B_ * N_) return;
    int n = idx & 511;
    int t2 = idx >> 9;
    int b = t2 & 31;
    int row = t2 >> 5;
    int t = row >> 1, c = row & 1;
    histT[(long)row * GT + b * 512 + n] =
        hd[(((long)b * L_ + t) * N_ + n) * 2 + c];
}

__global__ void dec_diff_k(const float* __restrict__ PT,
                           const float* __restrict__ dec,
                           float* __restrict__ TDEC) {
    int b = blockIdx.y;
    int r = blockIdx.x * 256 + threadIdx.x;
    __shared__ float ds[512];
    ds[threadIdx.x] = dec[b * 512 + threadIdx.x];
    ds[threadIdx.x + 256] = dec[b * 512 + threadIdx.x + 256];
    __syncthreads();
    const float* p = PT + (long)b * 512 * 2048 + r;
    float acc = 0.f;
    #pragma unroll 8
    for (int j = 0; j < 512; j++) acc += ds[j] * p[(long)j * 2048];
    TDEC[(long)b * 2048 + r] = acc;
}

__global__ void add_his_k(float* __restrict__ h0r, float* __restrict__ h0T,
                          float* __restrict__ h1r, float* __restrict__ h1T,
                          const float* __restrict__ his) {
    int i = blockIdx.x * blockDim.x + threadIdx.x;
    if (i >= B_ * N_ * U_) return;
    int grow = i >> 6, c = i & 63;
    float v = his[i];
    h0r[i] += v; h1r[i] += v;
    h0T[(long)c * GT + grow] += v;
    h1T[(long)c * GT + grow] += v;
}

__global__ void projT_k(const float* __restrict__ hT, const float* __restrict__ W,
                        const float* __restrict__ bptr, float* __restrict__ decin,
                        float* __restrict__ out, int t) {
    int grow = blockIdx.x * blockDim.x + threadIdx.x;
    if (grow >= B_ * N_) return;
    float s = bptr[0];
    #pragma unroll
    for (int c = 0; c < 64; c++) s += hT[(long)c * GT + grow] * W[c];
    decin[grow] = s;
    out[(long)grow * HOR + t] = s;
}

// ---------------------------------------------------------------------------
// Host orchestration
// ---------------------------------------------------------------------------
struct HPair { float* r; float* t; };

static void diff64(const float* src1, const float* PT, float* TT) {
    difft_k<64, 128, 8, 4, 3><<<dim3(16, 1, B_), 256>>>(64, 64, src1, nullptr, PT, TT, (long)64 * 2048);
}

// layer-0 cell: hx diffusion supplied externally (Tb, sTb).
static void cell0(float* S, int f_in,
                  const float* Xa, long sXa, int snXa, long sjXa,
                  const float* Ta, long sTa,
                  const float* Tb, long sTb,
                  HPair hx, HPair hout,
                  const float* Wg, const float* bg,
                  const float* Wc, const float* bc) {
    float* PT    = S + OFF_PT;
    float* TRHXT = S + OFF_TRHXT;
    float* RHXT  = S + OFF_RHXT;
    float* Ub    = S + OFF_U;
    int K = (f_in + 64) * 5;

    catgemmT_k<64, 128, 4, 8, 3><<<dim3(1, 256), 256>>>(
        K, f_in, Xa, sXa, snXa, sjXa, hx.t, Ta, sTa, Tb, sTb,
        Wg, 128, bg, hx.r, nullptr, RHXT, Ub, nullptr, nullptr, 0);
    diff64(RHXT, PT, TRHXT);
    catgemmT_k<64, 64, 4, 4, 4><<<dim3(1, 256), 256>>>(
        K, f_in, Xa, sXa, snXa, sjXa, RHXT, Ta, sTa, TRHXT, (long)64 * 2048,
        Wc, 64, bc, hx.r, Ub, nullptr, nullptr, hout.t, hout.r, 1);
}

// layer-1 cell: merged diffusion of [xinT ; hxT] into tcatt (ping-pong).
static void cell1(float* S, const float* xinT, HPair hx, HPair hout,
                  float* tcatt,
                  const float* Wg, const float* bg,
                  const float* Wc, const float* bc) {
    float* PT    = S + OFF_PT;
    float* TRHXT = S + OFF_TRHXT;
    float* RHXT  = S + OFF_RHXT;
    float* Ub    = S + OFF_U;
    const long sTC = (long)128 * 2048;
    int K = 640;

    difft_k<64, 128, 8, 4, 3><<<dim3(16, 2, B_), 256>>>(
        128, 64, xinT, hx.t, PT, tcatt, sTC);
    catgemmT_k<64, 128, 4, 8, 3><<<dim3(1, 256), 256>>>(
        K, 64, xinT, 512, 1, (long)GT, hx.t, tcatt, sTC, tcatt + 64 * 2048, sTC,
        Wg, 128, bg, hx.r, nullptr, RHXT, Ub, nullptr, nullptr, 0);
    diff64(RHXT, PT, TRHXT);
    catgemmT_k<64, 64, 4, 4, 4><<<dim3(1, 256), 256>>>(
        K, 64, xinT, 512, 1, (long)GT, RHXT, tcatt, sTC, TRHXT, (long)64 * 2048,
        Wc, 64, bc, hx.r, Ub, nullptr, nullptr, hout.t, hout.r, 1);
}

extern "C" void kernel_launch(void* const* d_in, const int* in_sizes, int n_in,
                              void* d_out, int out_size) {
    (void)in_sizes; (void)n_in; (void)out_size;
    float* S = nullptr;
    cudaGetSymbolAddress((void**)&S, g_scratch);

    const float* hd   = (const float*)d_in[0];
    const float* hs   = (const float*)d_in[1];
    const float* adj  = (const float*)d_in[2];
    const float* e0Wg = (const float*)d_in[3];
    const float* e0bg = (const float*)d_in[4];
    const float* e0Wc = (const float*)d_in[5];
    const float* e0bc = (const float*)d_in[6];
    const float* e1Wg = (const float*)d_in[7];
    const float* e1bg = (const float*)d_in[8];
    const float* e1Wc = (const float*)d_in[9];
    const float* e1bc = (const float*)d_in[10];
    const float* d0Wg = (const float*)d_in[11];
    const float* d0bg = (const float*)d_in[12];
    const float* d0Wc = (const float*)d_in[13];
    const float* d0bc = (const float*)d_in[14];
    const float* d1Wg = (const float*)d_in[15];
    const float* d1bg = (const float*)d_in[16];
    const float* d1Wc = (const float*)d_in[17];
    const float* d1bc = (const float*)d_in[18];
    const float* prW  = (const float*)d_in[19];
    const float* prb  = (const float*)d_in[20];
    const float* f1W  = (const float*)d_in[21];
    const float* f1b  = (const float*)d_in[22];
    const float* f2W  = (const float*)d_in[23];
    const float* f2b  = (const float*)d_in[24];
    float* out = (float*)d_out;

    float* A0T  = S + OFF_A0T;
    float* A1T  = S + OFF_A1T;
    float* PT   = S + OFF_PT;
    float* TCA  = S + OFF_TCA;
    float* TCB  = S + OFF_TCB;
    float* ZD   = S + OFF_ZD;
    float* THXT = S + OFF_THXT;
    float* TTX  = S + OFF_TTX;
    float* TDEC = S + OFF_TDEC;
    float* HISTT= S + OFF_HISTT;
    float* HIS  = S + OFF_HIS;
    float* FC1  = S + OFF_FC1;
    float* DEC  = S + OFF_DEC;
    float* RS0  = S + OFF_RS0;
    float* RS1  = S + OFF_RS1;

    HPair H[4];
    for (int i = 0; i < 4; i++) {
        H[i].r  = S + OFF_H + (2 * i) * SZ_H1;
        H[i].t  = S + OFF_H + (2 * i + 1) * SZ_H1;
    }

    cudaMemsetAsync(S + OFF_H, 0, 4 * SZ_H1 * sizeof(float));
    cudaMemsetAsync(DEC, 0, (long)B_ * N_ * sizeof(float));
    cudaMemsetAsync(ZD, 0, (long)B_ * 64 * 2048 * sizeof(float));

    // ---- supports + transposed stacked diffusion operator PT ----
    rowsum_k<<<(B_ * N_ * 32 + 255) / 256, 256>>>(adj, RS0);
    colsum_k<<<(B_ * N_ + 255) / 256, 256>>>(adj, RS1);
    fill_supports_T<<<(int)(((long)B_ * N_ * N_ + 255) / 256), 256>>>(adj, RS0, RS1, A0T, A1T, PT);
    const long NB = (long)N_ * N_;
    const long PBx = (long)512 * 2048;
    dim3 gp(4, 4, B_);
    sgemm_t<128, 128, 8, 8><<<gp, 256>>>(512, A0T, 512, NB, A0T, 512, NB,
                                         PT + 512, 2048, PBx, 1, nullptr, 0, nullptr);
    sgemm_t<128, 128, 8, 8><<<gp, 256>>>(512, A0T, 512, NB, A1T, 512, NB,
                                         PT + 1024, 2048, PBx, 0, nullptr, 0, nullptr);
    sgemm_t<128, 128, 8, 8><<<gp, 256>>>(512, PT + 1024, 2048, PBx, A1T, 512, NB,
                                         PT + 1536, 2048, PBx, 2, A0T, NB, nullptr);

    // ---- fc_his ----
    sgemm_t<128, 128, 8, 8><<<dim3(2, 128, 1), 256>>>(96, hs, 96, 0, f1W, 256, 0,
                                                      FC1, 256, 0, 3, nullptr, 0, f1b);
    sgemm_t<128, 64, 8, 4><<<dim3(1, 128, 1), 256>>>(256, FC1, 256, 0, f2W, 64, 0,
                                                     HIS, 64, 0, 3, nullptr, 0, f2b);

    // ---- encoder layer-0 input diffusions, all timesteps at once ----
    hist_t_k<<<(24 * B_ * N_ + 255) / 256, 256>>>(hd, HISTT);
    difft_k<64, 128, 8, 4, 3><<<dim3(16, 1, B_), 256>>>(24, 24, HISTT, nullptr, PT,
                                                        TTX, (long)24 * 2048);

    HPair hc0 = H[0], hc1 = H[1], hn0 = H[2], hn1 = H[3];
    float* prevTC = nullptr;

    // ---- encoder ----
    for (int t = 0; t < L_; t++) {
        const float* Tb = (t == 0) ? ZD : prevTC;
        long sTb = (t == 0) ? (long)64 * 2048 : (long)128 * 2048;
        cell0(S, 2,
              hd + (long)t * N_ * 2, (long)L_ * N_ * 2, 2, 1,
              TTX + (long)t * 2 * 2048, (long)24 * 2048,
              Tb, sTb,
              hc0, hn0, e0Wg, e0bg, e0Wc, e0bc);
        float* tc = (prevTC == TCA) ? TCB : TCA;
        cell1(S, hn0.t, hc1, hn1, tc, e1Wg, e1bg, e1Wc, e1bc);
        prevTC = tc;
        HPair tmp;
        tmp = hc0; hc0 = hn0; hn0 = tmp;
        tmp = hc1; hc1 = hn1; hn1 = tmp;
    }
    add_his_k<<<(B_ * N_ * U_ + 255) / 256, 256>>>(hc0.r, hc0.t, hc1.r, hc1.t, HIS);

    // ---- decoder ----
    for (int t = 0; t < HOR; t++) {
        dec_diff_k<<<dim3(8, B_), 256>>>(PT, DEC, TDEC);
        const float* Tb;
        long sTb;
        if (t == 0) {
            diff64(hc0.t, PT, THXT);
            Tb = THXT; sTb = (long)64 * 2048;
        } else {
            Tb = prevTC; sTb = (long)128 * 2048;
        }
        cell0(S, 1,
              DEC, 512, 1, 0,
              TDEC, (long)2048,
              Tb, sTb,
              hc0, hn0, d0Wg, d0bg, d0Wc, d0bc);
        float* tc = (prevTC == TCA) ? TCB : TCA;
        cell1(S, hn0.t, hc1, hn1, tc, d1Wg, d1bg, d1Wc, d1bc);
        prevTC = tc;
        projT_k<<<(B_ * N_ + 255) / 256, 256>>>(hn1.t, prW, prb, DEC, out, t);
        HPair tmp;
        tmp = hc0; hc0 = hn0; hn0 = tmp;
        tmp = hc1; hc1 = hn1; hn1 = tmp;
    }
}

// round 16
// speedup vs baseline: 1.0470x; 1.0081x over previous
#include <cuda_runtime.h>
#include <math.h>

#define B_  32
#define N_  512
#define L_  12
#define U_  64
#define HOR 12

// ---------------------------------------------------------------------------
// Scratch layout (floats)
// ---------------------------------------------------------------------------
constexpr long SZ_NN  = (long)B_ * N_ * N_;          // 8388608
constexpr long GT     = (long)B_ * N_;               // 16384

constexpr long OFF_A0T   = 0;
constexpr long OFF_A1T   = OFF_A0T + SZ_NN;
constexpr long OFF_PT    = OFF_A1T + SZ_NN;               // (B,512,2048)
constexpr long OFF_TCA   = OFF_PT + 4 * SZ_NN;            // (B,128,2048) ping
constexpr long OFF_TCB   = OFF_TCA + (long)B_*128*2048;   // (B,128,2048) pong
constexpr long OFF_ZD    = OFF_TCB + (long)B_*128*2048;   // (B,64,2048) zeros
constexpr long OFF_THXT  = OFF_ZD + (long)B_*64*2048;     // (B,64,2048) dec step0
constexpr long OFF_TRHXT = OFF_THXT + (long)B_*64*2048;   // (B,64,2048)
constexpr long OFF_TTX   = OFF_TRHXT + (long)B_*64*2048;  // (B,24,2048)
constexpr long OFF_TDEC  = OFF_TTX + (long)B_*24*2048;    // (B,2048)
constexpr long OFF_HISTT = OFF_TDEC + (long)B_*2048;      // (24,16384)
constexpr long OFF_U     = OFF_HISTT + 24*GT;             // (16384,64) row
constexpr long OFF_HIS   = OFF_U + 64*GT;                 // (16384,64) row
constexpr long OFF_FC1   = OFF_HIS + 64*GT;               // (16384,256)
constexpr long OFF_DEC   = OFF_FC1 + 256*GT;              // (16384)
constexpr long OFF_RS0   = OFF_DEC + GT;
constexpr long OFF_RS1   = OFF_RS0 + GT;
constexpr long OFF_RHXT  = OFF_RS1 + GT;                  // (64,16384)
constexpr long OFF_H     = OFF_RHXT + 64*GT;              // 8 buffers x 1M
constexpr long SZ_H1 = 64*GT;
constexpr long SCRATCH_TOTAL = OFF_H + 8*SZ_H1;

__device__ float g_scratch[SCRATCH_TOTAL];

// ---------------------------------------------------------------------------
// Support construction (transposed supports)
// ---------------------------------------------------------------------------
__global__ void rowsum_k(const float* __restrict__ adj, float* __restrict__ rs0) {
    int w = (blockIdx.x * blockDim.x + threadIdx.x) >> 5;
    int lane = threadIdx.x & 31;
    if (w >= B_ * N_) return;
    const float* base = adj + (long)w * N_;
    float s = 0.f;
    for (int j = lane; j < N_; j += 32) s += base[j];
    #pragma unroll
    for (int o = 16; o; o >>= 1) s += __shfl_xor_sync(0xffffffffu, s, o);
    if (lane == 0) rs0[w] = s + 1.0f;
}

__global__ void colsum_k(const float* __restrict__ adj, float* __restrict__ rs1) {
    int idx = blockIdx.x * blockDim.x + threadIdx.x;
    if (idx >= B_ * N_) return;
    int b = idx >> 9, i = idx & 511;
    const float* base = adj + (long)b * N_ * N_ + i;
    float s = 1.0f;
    for (int j = 0; j < N_; j++) s += base[(long)j * N_];
    rs1[idx] = s;
}

// Coalesced supports fill via 32x32 tile transpose.
// A0T[b][j][i] = (adj[b][i][j] + d)/rs0[i]  (staged through smem, both phases coalesced)
// A1T[b][j][i] = (adj[b][j][i] + d)/rs1[i]  (direct, coalesced in write phase)
// PT  block m=1: PT[b][j][i] = A0T value.
__global__ void fill_supports2(const float* __restrict__ adj,
                               const float* __restrict__ rs0,
                               const float* __restrict__ rs1,
                               float* __restrict__ A0T, float* __restrict__ A1T,
                               float* __restrict__ PT) {
    __shared__ float s[32][33];
    int b = blockIdx.z;
    int j0 = blockIdx.x * 32, i0 = blockIdx.y * 32;
    int tx = threadIdx.x, ty = threadIdx.y;        // block (32, 8)
    const float* ab = adj + (long)b * N_ * N_;
    #pragma unroll
    for (int r = 0; r < 4; r++) {
        int i = i0 + ty + r * 8;
        float a = ab[(long)i * N_ + j0 + tx];      // coalesced in j
        float d = (i == (j0 + tx)) ? 1.f : 0.f;
        s[ty + r * 8][tx] = (a + d) / rs0[b * N_ + i];
    }
    __syncthreads();
    #pragma unroll
    for (int r = 0; r < 4; r++) {
        int j = j0 + ty + r * 8;
        int i = i0 + tx;
        float v0 = s[tx][ty + r * 8];
        A0T[((long)b * N_ + j) * N_ + i] = v0;                      // coalesced in i
        PT[(long)b * 512 * 2048 + (long)j * 2048 + i] = v0;         // coalesced in i
        float at = ab[(long)j * N_ + i];                            // coalesced in i
        float dd = (i == j) ? 1.f : 0.f;
        A1T[((long)b * N_ + j) * N_ + i] = (at + dd) / rs1[b * N_ + i];
    }
}

// ---------------------------------------------------------------------------
// Generic batched SGEMM: C[b] = A[b] @ B[b], tile BMxBNx16.
// epi: 0 none, 1: 2x - I, 2: 2x - extra[b] (ld 512), 3: bias + relu
// ---------------------------------------------------------------------------
template<int BM, int BN, int TM, int TN, int MINB>
__global__ __launch_bounds__(256, MINB)
void sgemm_t(int K,
             const float* __restrict__ A, int lda, long sA,
             const float* __restrict__ Bm, int ldb, long sB,
             float* __restrict__ C, int ldc, long sC,
             int epi, const float* __restrict__ extra, long sE,
             const float* __restrict__ bias)
{
    constexpr int BK = 16;
    constexpr int TX = BN / TN;
    constexpr int AF = BM / 64;
    constexpr int BF = BN / 64;
    __shared__ float As[2][BK][BM + 4];
    __shared__ float Bs[2][BK][BN];
    int bz = blockIdx.z;
    const float* Ab = A + (long)bz * sA;
    const float* Bb = Bm + (long)bz * sB;
    float* Cb = C + (long)bz * sC;
    int row0 = blockIdx.y * BM, col0 = blockIdx.x * BN;
    int tid = threadIdx.x;
    int tx = tid % TX, ty = tid / TX;

    int aRow[AF], aCol[AF], bRow[BF], bCol[BF];
    #pragma unroll
    for (int s = 0; s < AF; s++) { int idx = tid + s * 256; aRow[s] = idx >> 2; aCol[s] = (idx & 3) << 2; }
    #pragma unroll
    for (int s = 0; s < BF; s++) { int idx = tid + s * 256; bRow[s] = idx / (BN / 4); bCol[s] = (idx % (BN / 4)) << 2; }

    float4 aR[AF], bR[BF];

    auto ldT = [&](int k0) {
        #pragma unroll
        for (int s = 0; s < AF; s++) {
            const float* p = Ab + (long)(row0 + aRow[s]) * lda + k0 + aCol[s];
            if (k0 + BK <= K) aR[s] = *(const float4*)p;
            else {
                int k = k0 + aCol[s];
                aR[s].x = (k     < K) ? p[0] : 0.f;
                aR[s].y = (k + 1 < K) ? p[1] : 0.f;
                aR[s].z = (k + 2 < K) ? p[2] : 0.f;
                aR[s].w = (k + 3 < K) ? p[3] : 0.f;
            }
        }
        #pragma unroll
        for (int s = 0; s < BF; s++) {
            int k = k0 + bRow[s];
            if (k < K) bR[s] = *(const float4*)(Bb + (long)k * ldb + col0 + bCol[s]);
            else bR[s] = make_float4(0.f, 0.f, 0.f, 0.f);
        }
    };
    auto stT = [&](int buf) {
        #pragma unroll
        for (int s = 0; s < AF; s++) {
            As[buf][aCol[s]    ][aRow[s]] = aR[s].x;
            As[buf][aCol[s] + 1][aRow[s]] = aR[s].y;
            As[buf][aCol[s] + 2][aRow[s]] = aR[s].z;
            As[buf][aCol[s] + 3][aRow[s]] = aR[s].w;
        }
        #pragma unroll
        for (int s = 0; s < BF; s++)
            *(float4*)&Bs[buf][bRow[s]][bCol[s]] = bR[s];
    };

    float acc[TM][TN];
    #pragma unroll
    for (int i = 0; i < TM; i++)
        #pragma unroll
        for (int j = 0; j < TN; j++) acc[i][j] = 0.f;

    int ntile = (K + BK - 1) / BK;
    ldT(0); stT(0); __syncthreads();
    for (int t = 0; t < ntile; t++) {
        if (t + 1 < ntile) ldT((t + 1) * BK);
        int buf = t & 1;
        #pragma unroll
        for (int kk = 0; kk < BK; kk++) {
            float ar[TM], br[TN];
            #pragma unroll
            for (int i = 0; i < TM / 4; i++)
                *(float4*)&ar[i * 4] = *(const float4*)&As[buf][kk][ty * TM + i * 4];
            #pragma unroll
            for (int j = 0; j < TN / 4; j++)
                *(float4*)&br[j * 4] = *(const float4*)&Bs[buf][kk][tx * TN + j * 4];
            #pragma unroll
            for (int i = 0; i < TM; i++)
                #pragma unroll
                for (int j = 0; j < TN; j++) acc[i][j] += ar[i] * br[j];
        }
        if (t + 1 < ntile) stT(buf ^ 1);
        __syncthreads();
    }

    #pragma unroll
    for (int i = 0; i < TM; i++) {
        int r = row0 + ty * TM + i;
        #pragma unroll
        for (int j = 0; j < TN; j++) {
            int c = col0 + tx * TN + j;
            float v = acc[i][j];
            if (epi == 1) v = 2.f * v - ((r == c) ? 1.f : 0.f);
            else if (epi == 2) v = 2.f * v - extra[(long)bz * sE + (long)r * N_ + c];
            else if (epi == 3) { v += bias[c]; v = fmaxf(v, 0.f); }
            Cb[(long)r * ldc + c] = v;
        }
    }
}

// ---------------------------------------------------------------------------
// Transposed diffusion GEMM (occupancy-tuned, min MINB blocks/SM):
//   TT[b](MR x 2048) = Aeff[b](MR x 512) @ PT[b](512 x 2048)
// ---------------------------------------------------------------------------
template<int BM, int BN, int TM, int TN, int MINB>
__global__ __launch_bounds__(256, MINB)
void difft_k(int MR, int asplit,
             const float* __restrict__ src1,
             const float* __restrict__ src2,
             const float* __restrict__ PT,
             float* __restrict__ TT, long sT)
{
    constexpr int BK = 16;
    constexpr int TX = BN / TN;
    constexpr int AE = BM * BK / 256;
    constexpr int BF = BK * BN / 1024;
    __shared__ float As[2][BK][BM + 4];
    __shared__ float Bs[2][BK][BN];

    int bz = blockIdx.z;
    int row0 = blockIdx.y * BM, col0 = blockIdx.x * BN;
    int tid = threadIdx.x;
    int tx = tid % TX, ty = tid / TX;

    int am = tid % BM;
    int ak0 = (tid / BM) * AE;
    int r = row0 + am;
    const float* srow = nullptr;
    if (r < asplit) srow = src1 + (long)r * GT + (long)bz * 512;
    else if (r < MR) srow = src2 + (long)(r - asplit) * GT + (long)bz * 512;

    int bRow[BF], bCol[BF];
    #pragma unroll
    for (int s = 0; s < BF; s++) {
        int idx = tid + s * 256;
        bRow[s] = idx / (BN / 4);
        bCol[s] = (idx % (BN / 4)) << 2;
    }

    float aR[AE];
    float4 bR[BF];
    const float* Pb = PT + (long)bz * 512 * 2048;

    auto ldT = [&](int k0) {
        if (srow) {
            #pragma unroll
            for (int e = 0; e < AE; e += 4)
                *(float4*)&aR[e] = *(const float4*)(srow + k0 + ak0 + e);
        } else {
            #pragma unroll
            for (int e = 0; e < AE; e++) aR[e] = 0.f;
        }
        #pragma unroll
        for (int s = 0; s < BF; s++)
            bR[s] = *(const float4*)(Pb + (long)(k0 + bRow[s]) * 2048 + col0 + bCol[s]);
    };
    auto stT = [&](int buf) {
        #pragma unroll
        for (int e = 0; e < AE; e++) As[buf][ak0 + e][am] = aR[e];
        #pragma unroll
        for (int s = 0; s < BF; s++) *(float4*)&Bs[buf][bRow[s]][bCol[s]] = bR[s];
    };

    float acc[TM][TN];
    #pragma unroll
    for (int i = 0; i < TM; i++)
        #pragma unroll
        for (int j = 0; j < TN; j++) acc[i][j] = 0.f;

    constexpr int NT = 512 / BK;
    ldT(0); stT(0); __syncthreads();
    for (int t = 0; t < NT; t++) {
        if (t + 1 < NT) ldT((t + 1) * BK);
        int buf = t & 1;
        #pragma unroll
        for (int kk = 0; kk < BK; kk++) {
            float ar[TM], br[TN];
            #pragma unroll
            for (int i = 0; i < TM / 4; i++)
                *(float4*)&ar[i * 4] = *(const float4*)&As[buf][kk][ty * TM + i * 4];
            #pragma unroll
            for (int j = 0; j < TN / 4; j++)
                *(float4*)&br[j * 4] = *(const float4*)&Bs[buf][kk][tx * TN + j * 4];
            #pragma unroll
            for (int i = 0; i < TM; i++)
                #pragma unroll
                for (int j = 0; j < TN; j++) acc[i][j] += ar[i] * br[j];
        }
        if (t + 1 < NT) stT(buf ^ 1);
        __syncthreads();
    }

    float* Tb = TT + (long)bz * sT;
    #pragma unroll
    for (int i = 0; i < TM; i++) {
        int rr = row0 + ty * TM + i;
        if (rr < MR) {
            #pragma unroll
            for (int j = 0; j < TN; j++) {
                int c = col0 + tx * TN + j;
                Tb[(long)rr * 2048 + c] = acc[i][j];
            }
        }
    }
}

// ---------------------------------------------------------------------------
// Contraction GEMM, transposed (coalesced) A-gather. MINB blocks/SM.
// ---------------------------------------------------------------------------
template<int BM, int BN, int TM, int TN, int MINB>
__global__ __launch_bounds__(256, MINB)
void catgemmT_k(int K, int f_in,
                const float* __restrict__ Xa, long sXa, int snXa, long sjXa,
                const float* __restrict__ XbT,
                const float* __restrict__ Ta, long sTa,
                const float* __restrict__ Tb, long sTb,
                const float* __restrict__ W, int ldW,
                const float* __restrict__ bias,
                const float* __restrict__ HXrow,
                const float* __restrict__ Urow,
                float* __restrict__ RHXT, float* __restrict__ Uout,
                float* __restrict__ HoutT, float* __restrict__ HoutR,
                int mode)
{
    constexpr int BK = 16;
    constexpr int TX = BN / TN;
    constexpr int AE = BM * BK / 256;
    constexpr int BF = BK * BN / 1024;
    __shared__ float As[2][BK][BM + 4];
    __shared__ float Bs[2][BK][BN];

    int row0 = blockIdx.y * BM;
    int col0 = blockIdx.x * BN;
    int tid = threadIdx.x;
    int tx = tid % TX, ty = tid / TX;

    int am = tid % BM;
    int ak0 = (tid / BM) * AE;
    int growL = row0 + am;
    int bL = growL >> 9, nL = growL & 511;

    int bRow[BF], bCol[BF];
    #pragma unroll
    for (int s = 0; s < BF; s++) {
        int idx = tid + s * 256;
        bRow[s] = idx / (BN / 4);
        bCol[s] = (idx % (BN / 4)) << 2;
    }

    float aR[AE];
    float4 bR[BF];

    auto ldT = [&](int k0) {
        #pragma unroll
        for (int e = 0; e < AE; e++) {
            int k = k0 + ak0 + e;
            float v = 0.f;
            if (k < K) {
                int j = k / 5;
                int m = k - j * 5;
                if (m == 0) {
                    v = (j < f_in) ? Xa[(long)bL * sXa + (long)nL * snXa + (long)j * sjXa]
                                   : XbT[(long)(j - f_in) * GT + growL];
                } else {
                    long off = (long)(m - 1) * 512 + nL;
                    v = (j < f_in) ? Ta[(long)bL * sTa + (long)j * 2048 + off]
                                   : Tb[(long)bL * sTb + (long)(j - f_in) * 2048 + off];
                }
            }
            aR[e] = v;
        }
        #pragma unroll
        for (int s = 0; s < BF; s++) {
            int k = k0 + bRow[s];
            if (k < K) bR[s] = *(const float4*)(W + (long)k * ldW + col0 + bCol[s]);
            else bR[s] = make_float4(0.f, 0.f, 0.f, 0.f);
        }
    };
    auto stT = [&](int buf) {
        #pragma unroll
        for (int e = 0; e < AE; e++) As[buf][ak0 + e][am] = aR[e];
        #pragma unroll
        for (int s = 0; s < BF; s++) *(float4*)&Bs[buf][bRow[s]][bCol[s]] = bR[s];
    };

    float acc[TM][TN];
    #pragma unroll
    for (int i = 0; i < TM; i++)
        #pragma unroll
        for (int j = 0; j < TN; j++) acc[i][j] = 0.f;

    int ntile = (K + BK - 1) / BK;
    ldT(0); stT(0); __syncthreads();
    for (int t = 0; t < ntile; t++) {
        if (t + 1 < ntile) ldT((t + 1) * BK);
        int buf = t & 1;
        #pragma unroll
        for (int kk = 0; kk < BK; kk++) {
            float ar[TM], br[TN];
            #pragma unroll
            for (int i = 0; i < TM / 4; i++)
                *(float4*)&ar[i * 4] = *(const float4*)&As[buf][kk][ty * TM + i * 4];
            #pragma unroll
            for (int j = 0; j < TN / 4; j++)
                *(float4*)&br[j * 4] = *(const float4*)&Bs[buf][kk][tx * TN + j * 4];
            #pragma unroll
            for (int i = 0; i < TM; i++)
                #pragma unroll
                for (int j = 0; j < TN; j++) acc[i][j] += ar[i] * br[j];
        }
        if (t + 1 < ntile) stT(buf ^ 1);
        __syncthreads();
    }

    #pragma unroll
    for (int i = 0; i < TM; i++) {
        int grow = row0 + ty * TM + i;
        #pragma unroll
        for (int j = 0; j < TN; j++) {
            int c = col0 + tx * TN + j;
            float v = acc[i][j] + bias[c];
            if (mode == 0) {
                v = 1.f / (1.f + expf(-v));
                if (c < 64) RHXT[(long)c * GT + grow] = v * HXrow[(long)grow * 64 + c];
                else        Uout[(long)grow * 64 + (c - 64)] = v;
            } else {
                float cc = tanhf(v);
                float u = Urow[(long)grow * 64 + c];
                float hx = HXrow[(long)grow * 64 + c];
                float h = u * hx + (1.f - u) * cc;
                HoutT[(long)c * GT + grow] = h;
                HoutR[(long)grow * 64 + c] = h;
            }
        }
    }
}

// ---------------------------------------------------------------------------
// Small kernels
// ---------------------------------------------------------------------------
__global__ void hist_t_k(const float* __restrict__ hd, float* __restrict__ histT) {
    int idx = blockIdx.x * blockDim.x + threadIdx.x;
    if (idx >= 24 * B_ * N_) return;
    int n = idx & 511;
    int t2 = idx >> 9;
    int b = t2 & 31;
    int row = t2 >> 5;
    int t = row >> 1, c = row & 1;
    histT[(long)row * GT + b * 512 + n] =
        hd[(((long)b * L_ + t) * N_ + n) * 2 + c];
}

__global__ void dec_diff_k(const float* __restrict__ PT,
                           const float* __restrict__ dec,
                           float* __restrict__ TDEC) {
    int b = blockIdx.y;
    int r = blockIdx.x * 256 + threadIdx.x;
    __shared__ float ds[512];
    ds[threadIdx.x] = dec[b * 512 + threadIdx.x];
    ds[threadIdx.x + 256] = dec[b * 512 + threadIdx.x + 256];
    __syncthreads();
    const float* p = PT + (long)b * 512 * 2048 + r;
    float acc = 0.f;
    #pragma unroll 8
    for (int j = 0; j < 512; j++) acc += ds[j] * p[(long)j * 2048];
    TDEC[(long)b * 2048 + r] = acc;
}

__global__ void add_his_k(float* __restrict__ h0r, float* __restrict__ h0T,
                          float* __restrict__ h1r, float* __restrict__ h1T,
                          const float* __restrict__ his) {
    int i = blockIdx.x * blockDim.x + threadIdx.x;
    if (i >= B_ * N_ * U_) return;
    int grow = i >> 6, c = i & 63;
    float v = his[i];
    h0r[i] += v; h1r[i] += v;
    h0T[(long)c * GT + grow] += v;
    h1T[(long)c * GT + grow] += v;
}

__global__ void projT_k(const float* __restrict__ hT, const float* __restrict__ W,
                        const float* __restrict__ bptr, float* __restrict__ decin,
                        float* __restrict__ out, int t) {
    int grow = blockIdx.x * blockDim.x + threadIdx.x;
    if (grow >= B_ * N_) return;
    float s = bptr[0];
    #pragma unroll
    for (int c = 0; c < 64; c++) s += hT[(long)c * GT + grow] * W[c];
    decin[grow] = s;
    out[(long)grow * HOR + t] = s;
}

// ---------------------------------------------------------------------------
// Host orchestration
// ---------------------------------------------------------------------------
struct HPair { float* r; float* t; };

static void diff64(const float* src1, const float* PT, float* TT) {
    difft_k<64, 128, 8, 4, 3><<<dim3(16, 1, B_), 256>>>(64, 64, src1, nullptr, PT, TT, (long)64 * 2048);
}

// layer-0 cell: hx diffusion supplied externally (Tb, sTb).
static void cell0(float* S, int f_in,
                  const float* Xa, long sXa, int snXa, long sjXa,
                  const float* Ta, long sTa,
                  const float* Tb, long sTb,
                  HPair hx, HPair hout,
                  const float* Wg, const float* bg,
                  const float* Wc, const float* bc) {
    float* PT    = S + OFF_PT;
    float* TRHXT = S + OFF_TRHXT;
    float* RHXT  = S + OFF_RHXT;
    float* Ub    = S + OFF_U;
    int K = (f_in + 64) * 5;

    catgemmT_k<64, 128, 4, 8, 3><<<dim3(1, 256), 256>>>(
        K, f_in, Xa, sXa, snXa, sjXa, hx.t, Ta, sTa, Tb, sTb,
        Wg, 128, bg, hx.r, nullptr, RHXT, Ub, nullptr, nullptr, 0);
    diff64(RHXT, PT, TRHXT);
    catgemmT_k<64, 64, 4, 4, 3><<<dim3(1, 256), 256>>>(
        K, f_in, Xa, sXa, snXa, sjXa, RHXT, Ta, sTa, TRHXT, (long)64 * 2048,
        Wc, 64, bc, hx.r, Ub, nullptr, nullptr, hout.t, hout.r, 1);
}

// layer-1 cell: merged diffusion of [xinT ; hxT] into tcatt (ping-pong).
static void cell1(float* S, const float* xinT, HPair hx, HPair hout,
                  float* tcatt,
                  const float* Wg, const float* bg,
                  const float* Wc, const float* bc) {
    float* PT    = S + OFF_PT;
    float* TRHXT = S + OFF_TRHXT;
    float* RHXT  = S + OFF_RHXT;
    float* Ub    = S + OFF_U;
    const long sTC = (long)128 * 2048;
    int K = 640;

    difft_k<64, 128, 8, 4, 3><<<dim3(16, 2, B_), 256>>>(
        128, 64, xinT, hx.t, PT, tcatt, sTC);
    catgemmT_k<64, 128, 4, 8, 3><<<dim3(1, 256), 256>>>(
        K, 64, xinT, 512, 1, (long)GT, hx.t, tcatt, sTC, tcatt + 64 * 2048, sTC,
        Wg, 128, bg, hx.r, nullptr, RHXT, Ub, nullptr, nullptr, 0);
    diff64(RHXT, PT, TRHXT);
    catgemmT_k<64, 64, 4, 4, 3><<<dim3(1, 256), 256>>>(
        K, 64, xinT, 512, 1, (long)GT, RHXT, tcatt, sTC, TRHXT, (long)64 * 2048,
        Wc, 64, bc, hx.r, Ub, nullptr, nullptr, hout.t, hout.r, 1);
}

extern "C" void kernel_launch(void* const* d_in, const int* in_sizes, int n_in,
                              void* d_out, int out_size) {
    (void)in_sizes; (void)n_in; (void)out_size;
    float* S = nullptr;
    cudaGetSymbolAddress((void**)&S, g_scratch);

    const float* hd   = (const float*)d_in[0];
    const float* hs   = (const float*)d_in[1];
    const float* adj  = (const float*)d_in[2];
    const float* e0Wg = (const float*)d_in[3];
    const float* e0bg = (const float*)d_in[4];
    const float* e0Wc = (const float*)d_in[5];
    const float* e0bc = (const float*)d_in[6];
    const float* e1Wg = (const float*)d_in[7];
    const float* e1bg = (const float*)d_in[8];
    const float* e1Wc = (const float*)d_in[9];
    const float* e1bc = (const float*)d_in[10];
    const float* d0Wg = (const float*)d_in[11];
    const float* d0bg = (const float*)d_in[12];
    const float* d0Wc = (const float*)d_in[13];
    const float* d0bc = (const float*)d_in[14];
    const float* d1Wg = (const float*)d_in[15];
    const float* d1bg = (const float*)d_in[16];
    const float* d1Wc = (const float*)d_in[17];
    const float* d1bc = (const float*)d_in[18];
    const float* prW  = (const float*)d_in[19];
    const float* prb  = (const float*)d_in[20];
    const float* f1W  = (const float*)d_in[21];
    const float* f1b  = (const float*)d_in[22];
    const float* f2W  = (const float*)d_in[23];
    const float* f2b  = (const float*)d_in[24];
    float* out = (float*)d_out;

    float* A0T  = S + OFF_A0T;
    float* A1T  = S + OFF_A1T;
    float* PT   = S + OFF_PT;
    float* TCA  = S + OFF_TCA;
    float* TCB  = S + OFF_TCB;
    float* ZD   = S + OFF_ZD;
    float* THXT = S + OFF_THXT;
    float* TTX  = S + OFF_TTX;
    float* TDEC = S + OFF_TDEC;
    float* HISTT= S + OFF_HISTT;
    float* HIS  = S + OFF_HIS;
    float* FC1  = S + OFF_FC1;
    float* DEC  = S + OFF_DEC;
    float* RS0  = S + OFF_RS0;
    float* RS1  = S + OFF_RS1;

    HPair H[4];
    for (int i = 0; i < 4; i++) {
        H[i].r  = S + OFF_H + (2 * i) * SZ_H1;
        H[i].t  = S + OFF_H + (2 * i + 1) * SZ_H1;
    }

    cudaMemsetAsync(S + OFF_H, 0, 4 * SZ_H1 * sizeof(float));
    cudaMemsetAsync(DEC, 0, (long)B_ * N_ * sizeof(float));
    cudaMemsetAsync(ZD, 0, (long)B_ * 64 * 2048 * sizeof(float));

    // ---- supports + transposed stacked diffusion operator PT ----
    rowsum_k<<<(B_ * N_ * 32 + 255) / 256, 256>>>(adj, RS0);
    colsum_k<<<(B_ * N_ + 255) / 256, 256>>>(adj, RS1);
    fill_supports2<<<dim3(16, 16, B_), dim3(32, 8)>>>(adj, RS0, RS1, A0T, A1T, PT);
    const long NB = (long)N_ * N_;
    const long PBx = (long)512 * 2048;
    dim3 gp(8, 4, B_);
    sgemm_t<128, 64, 8, 4, 3><<<gp, 256>>>(512, A0T, 512, NB, A0T, 512, NB,
                                           PT + 512, 2048, PBx, 1, nullptr, 0, nullptr);
    sgemm_t<128, 64, 8, 4, 3><<<gp, 256>>>(512, A0T, 512, NB, A1T, 512, NB,
                                           PT + 1024, 2048, PBx, 0, nullptr, 0, nullptr);
    sgemm_t<128, 64, 8, 4, 3><<<gp, 256>>>(512, PT + 1024, 2048, PBx, A1T, 512, NB,
                                           PT + 1536, 2048, PBx, 2, A0T, NB, nullptr);

    // ---- fc_his ----
    sgemm_t<128, 128, 8, 8, 2><<<dim3(2, 128, 1), 256>>>(96, hs, 96, 0, f1W, 256, 0,
                                                         FC1, 256, 0, 3, nullptr, 0, f1b);
    sgemm_t<128, 64, 8, 4, 3><<<dim3(1, 128, 1), 256>>>(256, FC1, 256, 0, f2W, 64, 0,
                                                        HIS, 64, 0, 3, nullptr, 0, f2b);

    // ---- encoder layer-0 input diffusions, all timesteps at once ----
    hist_t_k<<<(24 * B_ * N_ + 255) / 256, 256>>>(hd, HISTT);
    difft_k<64, 128, 8, 4, 3><<<dim3(16, 1, B_), 256>>>(24, 24, HISTT, nullptr, PT,
                                                        TTX, (long)24 * 2048);

    HPair hc0 = H[0], hc1 = H[1], hn0 = H[2], hn1 = H[3];
    float* prevTC = nullptr;

    // ---- encoder ----
    for (int t = 0; t < L_; t++) {
        const float* Tb = (t == 0) ? ZD : prevTC;
        long sTb = (t == 0) ? (long)64 * 2048 : (long)128 * 2048;
        cell0(S, 2,
              hd + (long)t * N_ * 2, (long)L_ * N_ * 2, 2, 1,
              TTX + (long)t * 2 * 2048, (long)24 * 2048,
              Tb, sTb,
              hc0, hn0, e0Wg, e0bg, e0Wc, e0bc);
        float* tc = (prevTC == TCA) ? TCB : TCA;
        cell1(S, hn0.t, hc1, hn1, tc, e1Wg, e1bg, e1Wc, e1bc);
        prevTC = tc;
        HPair tmp;
        tmp = hc0; hc0 = hn0; hn0 = tmp;
        tmp = hc1; hc1 = hn1; hn1 = tmp;
    }
    add_his_k<<<(B_ * N_ * U_ + 255) / 256, 256>>>(hc0.r, hc0.t, hc1.r, hc1.t, HIS);

    // ---- decoder ----
    for (int t = 0; t < HOR; t++) {
        dec_diff_k<<<dim3(8, B_), 256>>>(PT, DEC, TDEC);
        const float* Tb;
        long sTb;
        if (t == 0) {
            diff64(hc0.t, PT, THXT);
            Tb = THXT; sTb = (long)64 * 2048;
        } else {
            Tb = prevTC; sTb = (long)128 * 2048;
        }
        cell0(S, 1,
              DEC, 512, 1, 0,
              TDEC, (long)2048,
              Tb, sTb,
              hc0, hn0, d0Wg, d0bg, d0Wc, d0bc);
        float* tc = (prevTC == TCA) ? TCB : TCA;
        cell1(S, hn0.t, hc1, hn1, tc, d1Wg, d1bg, d1Wc, d1bc);
        prevTC = tc;
        projT_k<<<(B_ * N_ + 255) / 256, 256>>>(hn1.t, prW, prb, DEC, out, t);
        HPair tmp;
        tmp = hc0; hc0 = hn0; hn0 = tmp;
        tmp = hc1; hc1 = hn1; hn1 = tmp;
    }
}